// round 13
// baseline (speedup 1.0000x reference)
#include <cuda_runtime.h>
#include <cuda_bf16.h>
#include <math.h>
#include <stdint.h>

// ---------------------------------------------------------------------------
// TraditionalSpikingModel via HMMA (mma.sync bf16) — tcgen05 unavailable
// (harness emits compute_103 non-'a' PTX).
//
// Hidden layers: weights split w = hi(bf16) + lo(bf16), one GEMM with virtual
// K' = 2K (A pointer wraps at K) -> fp32-grade accuracy. Final layer hi-only.
// GEMM: 128x128x32, 8 warps, 4-stage cp.async pipeline, one barrier/K-step.
// Scans: 4 lanes/thread, float4 loads, depth-10 explicit prefetch (MLP fix).
// R12 fix: input_scan uint2 timestep stride was /8 (bytes) not /4 (bf16/uint2).
// ---------------------------------------------------------------------------

#define T_STEPS 500
#define BATCH   64
#define IN_DIM  440
#define IN_PAD  448
#define HID     1024
#define OUT_DIM 1944
#define MROWS   (T_STEPS * BATCH)        // 32000
#define QMAXF   7.0f
#define INV_SQRT_BN 0.9999950000374997f  // 1/sqrt(1 + 1e-5)

// ---------------- device scratch (allocation-free rule) --------------------
__device__ __nv_bfloat16 g_actIn[(size_t)MROWS * IN_PAD];
__device__ __nv_bfloat16 g_act0[(size_t)MROWS * HID];
__device__ __nv_bfloat16 g_act1[(size_t)MROWS * HID];
__device__ float         g_ws[(size_t)MROWS * HID];
__device__ __nv_bfloat16 g_w0cat[(size_t)HID * 2 * IN_PAD];
__device__ __nv_bfloat16 g_wscat[(size_t)3 * HID * 2 * HID];
__device__ __nv_bfloat16 g_wf[(size_t)OUT_DIM * HID];

// ---------------------------- small helpers --------------------------------
__device__ __forceinline__ uint32_t smem_u32(const void* p) {
    uint32_t a;
    asm("{ .reg .u64 t; cvta.to.shared.u64 t, %1; cvt.u32.u64 %0, t; }"
        : "=r"(a) : "l"(p));
    return a;
}

__device__ __forceinline__ void cp_async16(uint32_t dst, const void* src, uint32_t src_bytes) {
    asm volatile("cp.async.cg.shared.global [%0], [%1], 16, %2;"
                 :: "r"(dst), "l"(src), "r"(src_bytes) : "memory");
}
#define CP_COMMIT() asm volatile("cp.async.commit_group;" ::: "memory")
#define CP_WAIT(n)  asm volatile("cp.async.wait_group %0;" :: "n"(n) : "memory")

__device__ __forceinline__ void ldmatrix_x4(uint32_t& r0, uint32_t& r1,
                                            uint32_t& r2, uint32_t& r3,
                                            uint32_t addr) {
    asm volatile("ldmatrix.sync.aligned.m8n8.x4.shared.b16 {%0,%1,%2,%3}, [%4];"
                 : "=r"(r0), "=r"(r1), "=r"(r2), "=r"(r3) : "r"(addr));
}

__device__ __forceinline__ void mma_bf16(float* c, const uint32_t* a, const uint32_t* b) {
    asm volatile(
        "mma.sync.aligned.m16n8k16.row.col.f32.bf16.bf16.f32 "
        "{%0,%1,%2,%3}, {%4,%5,%6,%7}, {%8,%9}, {%0,%1,%2,%3};"
        : "+f"(c[0]), "+f"(c[1]), "+f"(c[2]), "+f"(c[3])
        : "r"(a[0]), "r"(a[1]), "r"(a[2]), "r"(a[3]), "r"(b[0]), "r"(b[1]));
}

// swizzled byte offset inside a 128x32 bf16 tile (row = 64B, 4x16B chunks)
__device__ __forceinline__ uint32_t tile_off(int r, int c4) {
    return (uint32_t)(r * 64 + ((c4 ^ ((r >> 1) & 3)) << 4));
}

// fsq step on a float4 lane group; returns spike float4
__device__ __forceinline__ float4 fsq4(const float4 v) {
    float4 o;
    o.x = fminf(fmaxf(rintf(v.x), 0.f), QMAXF);
    o.y = fminf(fmaxf(rintf(v.y), 0.f), QMAXF);
    o.z = fminf(fmaxf(rintf(v.z), 0.f), QMAXF);
    o.w = fminf(fmaxf(rintf(v.w), 0.f), QMAXF);
    return o;
}

// pack float4 -> 4 bf16 (8B)
__device__ __forceinline__ uint2 pack_bf16x4(const float4 o) {
    __nv_bfloat162 lo = __floats2bfloat162_rn(o.x, o.y);
    __nv_bfloat162 hi = __floats2bfloat162_rn(o.z, o.w);
    uint2 r;
    r.x = *(uint32_t*)&lo;
    r.y = *(uint32_t*)&hi;
    return r;
}

// ---------------------------------------------------------------------------
// Weight split: dst[n][k] = bf16_hi(w), dst[n][Kp + k] = bf16(w - hi)
// ---------------------------------------------------------------------------
__global__ void split_weights_kernel(const float* __restrict__ src,
                                     __nv_bfloat16* __restrict__ dst,
                                     int N, int K, int Kp) {
    int idx = blockIdx.x * blockDim.x + threadIdx.x;
    if (idx >= N * Kp) return;
    int n = idx / Kp, k = idx - n * Kp;
    float w = (k < K) ? src[(size_t)n * K + k] : 0.f;
    __nv_bfloat16 hi = __float2bfloat16(w);
    float lo = w - __bfloat162float(hi);
    dst[(size_t)n * (2 * Kp) + k]      = hi;
    dst[(size_t)n * (2 * Kp) + Kp + k] = __float2bfloat16(lo);
}

// plain fp32 -> bf16 convert (final-layer weights, hi only)
__global__ void convert_weights_kernel(const float* __restrict__ src,
                                       __nv_bfloat16* __restrict__ dst, int n) {
    int idx = blockIdx.x * blockDim.x + threadIdx.x;
    if (idx < n) dst[idx] = __float2bfloat16(src[idx]);
}

// ---------------------------------------------------------------------------
// Input scan -> bf16 spikes, padded to IN_PAD cols. 4 lanes/thread (float4),
// depth-10 prefetch batches (T=500 = 50 x 10).
// ---------------------------------------------------------------------------
#define CHUNK 10
__global__ void input_scan_kernel(const float* __restrict__ xs,
                                  __nv_bfloat16* __restrict__ spk) {
    const int L4 = BATCH * (IN_PAD / 4);   // 7168 thread-lanes
    int idx = blockIdx.x * blockDim.x + threadIdx.x;
    if (idx >= L4) return;
    const int b  = idx / (IN_PAD / 4);
    const int i4 = (idx - b * (IN_PAD / 4)) * 4;
    const bool valid = (i4 < IN_DIM);      // whole float4 in-range (440 % 4 == 0)
    const float* xp = xs + (size_t)b * IN_DIM + i4;
    uint2* op = (uint2*)(spk + (size_t)b * IN_PAD + i4);
    const int OSTRIDE = (BATCH * IN_PAD) / 4;   // uint2 (=4 bf16) per timestep
    float4 vmem = make_float4(0.f, 0.f, 0.f, 0.f);
    float4 x[CHUNK];

    for (int t0 = 0; t0 < T_STEPS; t0 += CHUNK) {
        #pragma unroll
        for (int j = 0; j < CHUNK; ++j)
            x[j] = valid ? *(const float4*)(xp + (size_t)(t0 + j) * (BATCH * IN_DIM))
                         : make_float4(0.f, 0.f, 0.f, 0.f);
        #pragma unroll
        for (int j = 0; j < CHUNK; ++j) {
            vmem.x += x[j].x; vmem.y += x[j].y;
            vmem.z += x[j].z; vmem.w += x[j].w;
            float4 o = fsq4(vmem);
            op[(size_t)(t0 + j) * OSTRIDE] = pack_bf16x4(o);
            vmem.x -= o.x; vmem.y -= o.y; vmem.z -= o.z; vmem.w -= o.w;
        }
    }
}

// ---------------------------------------------------------------------------
// LIF scan: fp32 ws in (float4), bf16 spikes out. 4 lanes/thread, depth-10
// prefetch. Arithmetic per lane identical to scalar version.
// ---------------------------------------------------------------------------
__global__ void lif_scan_kernel(const float* __restrict__ ws,
                                const float* __restrict__ taus,
                                __nv_bfloat16* __restrict__ spk) {
    const int L4 = (BATCH * HID) / 4;      // 16384
    int idx = blockIdx.x * blockDim.x + threadIdx.x;
    if (idx >= L4) return;
    const int h4 = (idx * 4) & (HID - 1);
    const float4 tau = *(const float4*)(taus + h4);
    const float4* wp = (const float4*)(ws) + idx;
    uint2* op = (uint2*)(spk) + idx;       // uint2 = 4 bf16; stride L4 per t

    float4 syn  = make_float4(0.f, 0.f, 0.f, 0.f);
    float4 vmem = make_float4(0.f, 0.f, 0.f, 0.f);
    float4 x[CHUNK];

    for (int t0 = 0; t0 < T_STEPS; t0 += CHUNK) {
        #pragma unroll
        for (int j = 0; j < CHUNK; ++j)
            x[j] = wp[(size_t)(t0 + j) * L4];
        #pragma unroll
        for (int j = 0; j < CHUNK; ++j) {
            syn.x = fmaf(tau.x, syn.x, x[j].x);
            syn.y = fmaf(tau.y, syn.y, x[j].y);
            syn.z = fmaf(tau.z, syn.z, x[j].z);
            syn.w = fmaf(tau.w, syn.w, x[j].w);
            vmem.x += syn.x; vmem.y += syn.y;
            vmem.z += syn.z; vmem.w += syn.w;
            float4 o = fsq4(vmem);
            op[(size_t)(t0 + j) * L4] = pack_bf16x4(o);
            vmem.x -= o.x; vmem.y -= o.y; vmem.z -= o.z; vmem.w -= o.w;
        }
    }
}

// ---------------------------------------------------------------------------
// HMMA GEMM + fused BN over virtual Kv (hi|lo concat or plain):
//   C[m,n] = (sum_k A[m, k % Kphys] * B[n, k]) * gamma[n]*INV + beta[n]
// CTA 128x128, BK=32, 256 thr (8 warps 4x2, warp tile 32x64).
// 4-stage cp.async pipeline, ONE barrier per K-step.
// ---------------------------------------------------------------------------
__global__ void __launch_bounds__(256, 2)
gemm_hmma_kernel(const __nv_bfloat16* __restrict__ A,
                 const __nv_bfloat16* __restrict__ B,
                 const float* __restrict__ gamma,
                 const float* __restrict__ beta,
                 float* __restrict__ C,
                 int N, int Nld, int Kphys, int Kv, int Bstride) {
    extern __shared__ __align__(128) char smem[];
    const uint32_t sm0 = smem_u32(smem);   // A stages at 0..32KB, B at 32..64KB

    const int tid  = threadIdx.x;
    const int wid  = tid >> 5;
    const int lane = tid & 31;
    const int wm   = wid & 3;
    const int wn   = wid >> 2;
    const int m0   = blockIdx.y * 128;
    const int n0   = blockIdx.x * 128;

    const int nsteps = Kv / 32;

    const int r0 = tid >> 2;
    const int c4 = tid & 3;

    const int brow0 = n0 + r0, brow1 = n0 + r0 + 64;
    const uint32_t bsz0 = (brow0 < N) ? 16u : 0u;
    const uint32_t bsz1 = (brow1 < N) ? 16u : 0u;
    const __nv_bfloat16* Bp0 = B + (size_t)min(brow0, N - 1) * Bstride + c4 * 8;
    const __nv_bfloat16* Bp1 = B + (size_t)min(brow1, N - 1) * Bstride + c4 * 8;
    const __nv_bfloat16* Ap0 = A + (size_t)(m0 + r0) * Kphys + c4 * 8;
    const __nv_bfloat16* Ap1 = A + (size_t)(m0 + r0 + 64) * Kphys + c4 * 8;
    const uint32_t dA0 = tile_off(r0, c4), dA1 = tile_off(r0 + 64, c4);

    #define ISSUE_LOAD(s)                                                        \
    do {                                                                         \
        int k0 = (s) * 32;                                                       \
        int kA = (k0 >= Kphys) ? (k0 - Kphys) : k0;                              \
        uint32_t aB = sm0 + (uint32_t)((s) & 3) * 8192u;                         \
        uint32_t bB = aB + 32768u;                                               \
        cp_async16(aB + dA0, Ap0 + kA, 16u);                                     \
        cp_async16(aB + dA1, Ap1 + kA, 16u);                                     \
        cp_async16(bB + dA0, Bp0 + k0, bsz0);                                    \
        cp_async16(bB + dA1, Bp1 + k0, bsz1);                                    \
        CP_COMMIT();                                                             \
    } while (0)

    const int aRow = wm * 32 + (lane & 15);
    const int aKc  = lane >> 4;
    const int bRow = wn * 64 + (lane & 7) + ((lane >> 4) << 3);
    const int bKc  = (lane >> 3) & 1;

    float acc[2][8][4];
    #pragma unroll
    for (int i = 0; i < 2; ++i)
        #pragma unroll
        for (int j = 0; j < 8; ++j)
            #pragma unroll
            for (int q = 0; q < 4; ++q) acc[i][j][q] = 0.f;

    ISSUE_LOAD(0);
    ISSUE_LOAD(1);
    ISSUE_LOAD(2);

    for (int s = 0; s < nsteps; ++s) {
        if (s + 2 < nsteps)      { CP_WAIT(2); }
        else if (s + 1 < nsteps) { CP_WAIT(1); }
        else                     { CP_WAIT(0); }
        __syncthreads();
        if (s + 3 < nsteps) ISSUE_LOAD(s + 3);

        const uint32_t sAb = sm0 + (uint32_t)(s & 3) * 8192u;
        const uint32_t sBb = sAb + 32768u;

        #pragma unroll
        for (int ks = 0; ks < 2; ++ks) {
            uint32_t a[2][4], b[4][4];
            #pragma unroll
            for (int i = 0; i < 2; ++i) {
                int rr = aRow + i * 16;
                uint32_t ad = sAb + tile_off(rr, ks * 2 + aKc);
                ldmatrix_x4(a[i][0], a[i][1], a[i][2], a[i][3], ad);
            }
            #pragma unroll
            for (int p = 0; p < 4; ++p) {
                int rr = bRow + p * 16;
                uint32_t bd = sBb + tile_off(rr, ks * 2 + bKc);
                ldmatrix_x4(b[p][0], b[p][1], b[p][2], b[p][3], bd);
            }
            #pragma unroll
            for (int i = 0; i < 2; ++i)
                #pragma unroll
                for (int p = 0; p < 4; ++p) {
                    mma_bf16(acc[i][2 * p],     a[i], &b[p][0]);
                    mma_bf16(acc[i][2 * p + 1], a[i], &b[p][2]);
                }
        }
    }
    #undef ISSUE_LOAD

    // ---- epilogue: fused BN, float2 stores ----
    const int colBase = n0 + wn * 64 + (lane & 3) * 2;
    float sc[8][2], bi[8][2];
    #pragma unroll
    for (int j = 0; j < 8; ++j) {
        int col = colBase + j * 8;
        bool v = col < N;
        sc[j][0] = v ? gamma[col] * INV_SQRT_BN : 0.f;
        sc[j][1] = v ? gamma[col + 1] * INV_SQRT_BN : 0.f;
        bi[j][0] = v ? beta[col] : 0.f;
        bi[j][1] = v ? beta[col + 1] : 0.f;
    }

    const int rowBase = m0 + wm * 32 + (lane >> 2);
    #pragma unroll
    for (int i = 0; i < 2; ++i) {
        int row0 = rowBase + i * 16;
        int row1 = row0 + 8;
        #pragma unroll
        for (int j = 0; j < 8; ++j) {
            int col = colBase + j * 8;
            if (col < N) {
                float2 v0, v1;
                v0.x = fmaf(acc[i][j][0], sc[j][0], bi[j][0]);
                v0.y = fmaf(acc[i][j][1], sc[j][1], bi[j][1]);
                v1.x = fmaf(acc[i][j][2], sc[j][0], bi[j][0]);
                v1.y = fmaf(acc[i][j][3], sc[j][1], bi[j][1]);
                *(float2*)(C + (size_t)row0 * Nld + col) = v0;
                *(float2*)(C + (size_t)row1 * Nld + col) = v1;
            }
        }
    }
}

// ---------------------------------------------------------------------------
// In-place row-wise log_softmax over OUT_DIM=1944. One block (256 thr) / row.
// ---------------------------------------------------------------------------
__global__ void logsoftmax_kernel(float* __restrict__ out) {
    const int N = OUT_DIM;
    float* row = out + (size_t)blockIdx.x * N;
    const int tid = threadIdx.x;

    float v[8];
    float mx = -1e30f;
    #pragma unroll
    for (int j = 0; j < 8; ++j) {
        int c = tid + j * 256;
        v[j] = (c < N) ? row[c] : -1e30f;
        mx = fmaxf(mx, v[j]);
    }

    __shared__ float red_max[8];
    __shared__ float red_sum[8];
    #pragma unroll
    for (int o = 16; o > 0; o >>= 1)
        mx = fmaxf(mx, __shfl_xor_sync(0xffffffffu, mx, o));
    if ((tid & 31) == 0) red_max[tid >> 5] = mx;
    __syncthreads();
    mx = red_max[0];
    #pragma unroll
    for (int w = 1; w < 8; ++w) mx = fmaxf(mx, red_max[w]);

    float s = 0.f;
    #pragma unroll
    for (int j = 0; j < 8; ++j) s += expf(v[j] - mx);
    #pragma unroll
    for (int o = 16; o > 0; o >>= 1)
        s += __shfl_xor_sync(0xffffffffu, s, o);
    if ((tid & 31) == 0) red_sum[tid >> 5] = s;
    __syncthreads();
    s = 0.f;
    #pragma unroll
    for (int w = 0; w < 8; ++w) s += red_sum[w];

    const float lse = mx + logf(s);
    #pragma unroll
    for (int j = 0; j < 8; ++j) {
        int c = tid + j * 256;
        if (c < N) row[c] = v[j] - lse;
    }
}

// ---------------------------------------------------------------------------
// Launch sequence
// ---------------------------------------------------------------------------
#define GEMM_SMEM 65536

extern "C" void kernel_launch(void* const* d_in, const int* in_sizes, int n_in,
                              void* d_out, int out_size) {
    const float* xs   = (const float*)d_in[0];
    const float* W0   = (const float*)d_in[1];
    const float* Ws   = (const float*)d_in[2];
    const float* taus = (const float*)d_in[3];
    const float* bng  = (const float*)d_in[4];
    const float* bnb  = (const float*)d_in[5];
    const float* Wf   = (const float*)d_in[6];
    const float* fg   = (const float*)d_in[7];
    const float* fb   = (const float*)d_in[8];
    float* out = (float*)d_out;

    __nv_bfloat16 *actIn, *act0, *act1, *w0cat, *wscat, *wf;
    float* wsb;
    cudaGetSymbolAddress((void**)&actIn, g_actIn);
    cudaGetSymbolAddress((void**)&act0,  g_act0);
    cudaGetSymbolAddress((void**)&act1,  g_act1);
    cudaGetSymbolAddress((void**)&wsb,   g_ws);
    cudaGetSymbolAddress((void**)&w0cat, g_w0cat);
    cudaGetSymbolAddress((void**)&wscat, g_wscat);
    cudaGetSymbolAddress((void**)&wf,    g_wf);

    cudaFuncSetAttribute(gemm_hmma_kernel,
                         cudaFuncAttributeMaxDynamicSharedMemorySize, GEMM_SMEM);

    // weight preparation
    split_weights_kernel<<<(HID * IN_PAD + 255) / 256, 256>>>(
        W0, w0cat, HID, IN_DIM, IN_PAD);
    split_weights_kernel<<<(3 * HID * HID + 255) / 256, 256>>>(
        Ws, wscat, 3 * HID, HID, HID);
    convert_weights_kernel<<<(OUT_DIM * HID + 255) / 256, 256>>>(
        Wf, wf, OUT_DIM * HID);

    // input spike quantization scan (4 lanes/thread)
    input_scan_kernel<<<(BATCH * (IN_PAD / 4) + 127) / 128, 128>>>(xs, actIn);

    const dim3 grid_h(HID / 128, MROWS / 128);   // 8 x 250

    // layer 0 (Kphys = 448 padded, Kv = 896 hi|lo)
    gemm_hmma_kernel<<<grid_h, 256, GEMM_SMEM>>>(
        actIn, w0cat, bng, bnb, wsb, HID, HID, IN_PAD, 2 * IN_PAD, 2 * IN_PAD);
    lif_scan_kernel<<<(BATCH * HID / 4) / 128, 128>>>(wsb, taus, act0);

    // layers 1..3 (ping-pong), Kv = 2048 hi|lo
    __nv_bfloat16* src = act0;
    __nv_bfloat16* dst = act1;
    for (int l = 1; l < 4; ++l) {
        gemm_hmma_kernel<<<grid_h, 256, GEMM_SMEM>>>(
            src, wscat + (size_t)(l - 1) * HID * 2 * HID,
            bng + l * HID, bnb + l * HID, wsb, HID, HID, HID, 2 * HID, 2 * HID);
        lif_scan_kernel<<<(BATCH * HID / 4) / 128, 128>>>(wsb, taus + l * HID, dst);
        __nv_bfloat16* tmp = src; src = dst; dst = tmp;
    }

    // final GEMM (hi-only bf16 weights, Kv = 1024) + BN into d_out
    gemm_hmma_kernel<<<dim3((OUT_DIM + 127) / 128, MROWS / 128), 256, GEMM_SMEM>>>(
        src, wf, fg, fb, out, OUT_DIM, OUT_DIM, HID, HID, HID);
    logsoftmax_kernel<<<MROWS, 256>>>(out);
}

// round 14
// speedup vs baseline: 1.1752x; 1.1752x over previous
#include <cuda_runtime.h>
#include <cuda_bf16.h>
#include <math.h>
#include <stdint.h>

// ---------------------------------------------------------------------------
// TraditionalSpikingModel via HMMA (mma.sync bf16) — tcgen05 unavailable
// (harness emits compute_103 non-'a' PTX).
//
// Hidden layers: weights split w = hi(bf16) + lo(bf16), one GEMM with virtual
// K' = 2K (A pointer wraps at K) -> fp32-grade accuracy. Final layer hi-only.
// GEMM: 128x128x32, 8 warps, 4-stage cp.async pipeline, one barrier/K-step.
// Scans (R14): scalar 1 lane/thread (full thread count, 512/220 blocks) with
// EXPLICIT depth-10 prefetch arrays to force load batching (R13 proved ptxas
// won't batch across the loop-carried chain on its own; R13's mistake was
// cutting thread count 4x, starving the chip).
// ---------------------------------------------------------------------------

#define T_STEPS 500
#define BATCH   64
#define IN_DIM  440
#define IN_PAD  448
#define HID     1024
#define OUT_DIM 1944
#define MROWS   (T_STEPS * BATCH)        // 32000
#define QMAXF   7.0f
#define INV_SQRT_BN 0.9999950000374997f  // 1/sqrt(1 + 1e-5)
#define CHUNK   10

// ---------------- device scratch (allocation-free rule) --------------------
__device__ __nv_bfloat16 g_actIn[(size_t)MROWS * IN_PAD];
__device__ __nv_bfloat16 g_act0[(size_t)MROWS * HID];
__device__ __nv_bfloat16 g_act1[(size_t)MROWS * HID];
__device__ float         g_ws[(size_t)MROWS * HID];
__device__ __nv_bfloat16 g_w0cat[(size_t)HID * 2 * IN_PAD];
__device__ __nv_bfloat16 g_wscat[(size_t)3 * HID * 2 * HID];
__device__ __nv_bfloat16 g_wf[(size_t)OUT_DIM * HID];

// ---------------------------- small helpers --------------------------------
__device__ __forceinline__ uint32_t smem_u32(const void* p) {
    uint32_t a;
    asm("{ .reg .u64 t; cvta.to.shared.u64 t, %1; cvt.u32.u64 %0, t; }"
        : "=r"(a) : "l"(p));
    return a;
}

__device__ __forceinline__ void cp_async16(uint32_t dst, const void* src, uint32_t src_bytes) {
    asm volatile("cp.async.cg.shared.global [%0], [%1], 16, %2;"
                 :: "r"(dst), "l"(src), "r"(src_bytes) : "memory");
}
#define CP_COMMIT() asm volatile("cp.async.commit_group;" ::: "memory")
#define CP_WAIT(n)  asm volatile("cp.async.wait_group %0;" :: "n"(n) : "memory")

__device__ __forceinline__ void ldmatrix_x4(uint32_t& r0, uint32_t& r1,
                                            uint32_t& r2, uint32_t& r3,
                                            uint32_t addr) {
    asm volatile("ldmatrix.sync.aligned.m8n8.x4.shared.b16 {%0,%1,%2,%3}, [%4];"
                 : "=r"(r0), "=r"(r1), "=r"(r2), "=r"(r3) : "r"(addr));
}

__device__ __forceinline__ void mma_bf16(float* c, const uint32_t* a, const uint32_t* b) {
    asm volatile(
        "mma.sync.aligned.m16n8k16.row.col.f32.bf16.bf16.f32 "
        "{%0,%1,%2,%3}, {%4,%5,%6,%7}, {%8,%9}, {%0,%1,%2,%3};"
        : "+f"(c[0]), "+f"(c[1]), "+f"(c[2]), "+f"(c[3])
        : "r"(a[0]), "r"(a[1]), "r"(a[2]), "r"(a[3]), "r"(b[0]), "r"(b[1]));
}

// swizzled byte offset inside a 128x32 bf16 tile (row = 64B, 4x16B chunks)
__device__ __forceinline__ uint32_t tile_off(int r, int c4) {
    return (uint32_t)(r * 64 + ((c4 ^ ((r >> 1) & 3)) << 4));
}

// ---------------------------------------------------------------------------
// Weight split: dst[n][k] = bf16_hi(w), dst[n][Kp + k] = bf16(w - hi)
// ---------------------------------------------------------------------------
__global__ void split_weights_kernel(const float* __restrict__ src,
                                     __nv_bfloat16* __restrict__ dst,
                                     int N, int K, int Kp) {
    int idx = blockIdx.x * blockDim.x + threadIdx.x;
    if (idx >= N * Kp) return;
    int n = idx / Kp, k = idx - n * Kp;
    float w = (k < K) ? src[(size_t)n * K + k] : 0.f;
    __nv_bfloat16 hi = __float2bfloat16(w);
    float lo = w - __bfloat162float(hi);
    dst[(size_t)n * (2 * Kp) + k]      = hi;
    dst[(size_t)n * (2 * Kp) + Kp + k] = __float2bfloat16(lo);
}

// plain fp32 -> bf16 convert (final-layer weights, hi only)
__global__ void convert_weights_kernel(const float* __restrict__ src,
                                       __nv_bfloat16* __restrict__ dst, int n) {
    int idx = blockIdx.x * blockDim.x + threadIdx.x;
    if (idx < n) dst[idx] = __float2bfloat16(src[idx]);
}

// ---------------------------------------------------------------------------
// Input scan -> bf16 spikes, padded to IN_PAD cols. Scalar lane/thread,
// explicit depth-10 prefetch (T=500 = 50 x 10).
// ---------------------------------------------------------------------------
__global__ void input_scan_kernel(const float* __restrict__ xs,
                                  __nv_bfloat16* __restrict__ spk) {
    const int L = BATCH * IN_PAD;
    int idx = blockIdx.x * blockDim.x + threadIdx.x;
    if (idx >= L) return;
    int b = idx / IN_PAD, i = idx - b * IN_PAD;
    const bool valid = (i < IN_DIM);
    const float* xp = xs + (size_t)b * IN_DIM + i;
    float vmem = 0.f;
    float x[CHUNK];

    for (int t0 = 0; t0 < T_STEPS; t0 += CHUNK) {
        #pragma unroll
        for (int j = 0; j < CHUNK; ++j)
            x[j] = valid ? xp[(size_t)(t0 + j) * (BATCH * IN_DIM)] : 0.f;
        #pragma unroll
        for (int j = 0; j < CHUNK; ++j) {
            vmem += x[j];
            float o = fminf(fmaxf(rintf(vmem), 0.f), QMAXF);
            spk[(size_t)(t0 + j) * L + idx] = __float2bfloat16(o);
            vmem -= o;
        }
    }
}

// ---------------------------------------------------------------------------
// LIF scan: fp32 ws in, bf16 spikes out. Scalar lane/thread, explicit
// depth-10 prefetch. Arithmetic order identical to the R9 scalar version.
// ---------------------------------------------------------------------------
__global__ void lif_scan_kernel(const float* __restrict__ ws,
                                const float* __restrict__ taus,
                                __nv_bfloat16* __restrict__ spk) {
    const int L = BATCH * HID;
    int idx = blockIdx.x * blockDim.x + threadIdx.x;
    if (idx >= L) return;
    const float tau = taus[idx & (HID - 1)];
    float syn = 0.f, vmem = 0.f;
    float x[CHUNK];

    for (int t0 = 0; t0 < T_STEPS; t0 += CHUNK) {
        #pragma unroll
        for (int j = 0; j < CHUNK; ++j)
            x[j] = ws[(size_t)(t0 + j) * L + idx];
        #pragma unroll
        for (int j = 0; j < CHUNK; ++j) {
            syn = fmaf(tau, syn, x[j]);
            vmem += syn;
            float o = fminf(fmaxf(rintf(vmem), 0.f), QMAXF);
            spk[(size_t)(t0 + j) * L + idx] = __float2bfloat16(o);
            vmem -= o;
        }
    }
}

// ---------------------------------------------------------------------------
// HMMA GEMM + fused BN over virtual Kv (hi|lo concat or plain):
//   C[m,n] = (sum_k A[m, k % Kphys] * B[n, k]) * gamma[n]*INV + beta[n]
// CTA 128x128, BK=32, 256 thr (8 warps 4x2, warp tile 32x64).
// 4-stage cp.async pipeline, ONE barrier per K-step.
// ---------------------------------------------------------------------------
__global__ void __launch_bounds__(256, 2)
gemm_hmma_kernel(const __nv_bfloat16* __restrict__ A,
                 const __nv_bfloat16* __restrict__ B,
                 const float* __restrict__ gamma,
                 const float* __restrict__ beta,
                 float* __restrict__ C,
                 int N, int Nld, int Kphys, int Kv, int Bstride) {
    extern __shared__ __align__(128) char smem[];
    const uint32_t sm0 = smem_u32(smem);   // A stages at 0..32KB, B at 32..64KB

    const int tid  = threadIdx.x;
    const int wid  = tid >> 5;
    const int lane = tid & 31;
    const int wm   = wid & 3;
    const int wn   = wid >> 2;
    const int m0   = blockIdx.y * 128;
    const int n0   = blockIdx.x * 128;

    const int nsteps = Kv / 32;

    const int r0 = tid >> 2;
    const int c4 = tid & 3;

    const int brow0 = n0 + r0, brow1 = n0 + r0 + 64;
    const uint32_t bsz0 = (brow0 < N) ? 16u : 0u;
    const uint32_t bsz1 = (brow1 < N) ? 16u : 0u;
    const __nv_bfloat16* Bp0 = B + (size_t)min(brow0, N - 1) * Bstride + c4 * 8;
    const __nv_bfloat16* Bp1 = B + (size_t)min(brow1, N - 1) * Bstride + c4 * 8;
    const __nv_bfloat16* Ap0 = A + (size_t)(m0 + r0) * Kphys + c4 * 8;
    const __nv_bfloat16* Ap1 = A + (size_t)(m0 + r0 + 64) * Kphys + c4 * 8;
    const uint32_t dA0 = tile_off(r0, c4), dA1 = tile_off(r0 + 64, c4);

    #define ISSUE_LOAD(s)                                                        \
    do {                                                                         \
        int k0 = (s) * 32;                                                       \
        int kA = (k0 >= Kphys) ? (k0 - Kphys) : k0;                              \
        uint32_t aB = sm0 + (uint32_t)((s) & 3) * 8192u;                         \
        uint32_t bB = aB + 32768u;                                               \
        cp_async16(aB + dA0, Ap0 + kA, 16u);                                     \
        cp_async16(aB + dA1, Ap1 + kA, 16u);                                     \
        cp_async16(bB + dA0, Bp0 + k0, bsz0);                                    \
        cp_async16(bB + dA1, Bp1 + k0, bsz1);                                    \
        CP_COMMIT();                                                             \
    } while (0)

    const int aRow = wm * 32 + (lane & 15);
    const int aKc  = lane >> 4;
    const int bRow = wn * 64 + (lane & 7) + ((lane >> 4) << 3);
    const int bKc  = (lane >> 3) & 1;

    float acc[2][8][4];
    #pragma unroll
    for (int i = 0; i < 2; ++i)
        #pragma unroll
        for (int j = 0; j < 8; ++j)
            #pragma unroll
            for (int q = 0; q < 4; ++q) acc[i][j][q] = 0.f;

    ISSUE_LOAD(0);
    ISSUE_LOAD(1);
    ISSUE_LOAD(2);

    for (int s = 0; s < nsteps; ++s) {
        if (s + 2 < nsteps)      { CP_WAIT(2); }
        else if (s + 1 < nsteps) { CP_WAIT(1); }
        else                     { CP_WAIT(0); }
        __syncthreads();
        if (s + 3 < nsteps) ISSUE_LOAD(s + 3);

        const uint32_t sAb = sm0 + (uint32_t)(s & 3) * 8192u;
        const uint32_t sBb = sAb + 32768u;

        #pragma unroll
        for (int ks = 0; ks < 2; ++ks) {
            uint32_t a[2][4], b[4][4];
            #pragma unroll
            for (int i = 0; i < 2; ++i) {
                int rr = aRow + i * 16;
                uint32_t ad = sAb + tile_off(rr, ks * 2 + aKc);
                ldmatrix_x4(a[i][0], a[i][1], a[i][2], a[i][3], ad);
            }
            #pragma unroll
            for (int p = 0; p < 4; ++p) {
                int rr = bRow + p * 16;
                uint32_t bd = sBb + tile_off(rr, ks * 2 + bKc);
                ldmatrix_x4(b[p][0], b[p][1], b[p][2], b[p][3], bd);
            }
            #pragma unroll
            for (int i = 0; i < 2; ++i)
                #pragma unroll
                for (int p = 0; p < 4; ++p) {
                    mma_bf16(acc[i][2 * p],     a[i], &b[p][0]);
                    mma_bf16(acc[i][2 * p + 1], a[i], &b[p][2]);
                }
        }
    }
    #undef ISSUE_LOAD

    // ---- epilogue: fused BN, float2 stores ----
    const int colBase = n0 + wn * 64 + (lane & 3) * 2;
    float sc[8][2], bi[8][2];
    #pragma unroll
    for (int j = 0; j < 8; ++j) {
        int col = colBase + j * 8;
        bool v = col < N;
        sc[j][0] = v ? gamma[col] * INV_SQRT_BN : 0.f;
        sc[j][1] = v ? gamma[col + 1] * INV_SQRT_BN : 0.f;
        bi[j][0] = v ? beta[col] : 0.f;
        bi[j][1] = v ? beta[col + 1] : 0.f;
    }

    const int rowBase = m0 + wm * 32 + (lane >> 2);
    #pragma unroll
    for (int i = 0; i < 2; ++i) {
        int row0 = rowBase + i * 16;
        int row1 = row0 + 8;
        #pragma unroll
        for (int j = 0; j < 8; ++j) {
            int col = colBase + j * 8;
            if (col < N) {
                float2 v0, v1;
                v0.x = fmaf(acc[i][j][0], sc[j][0], bi[j][0]);
                v0.y = fmaf(acc[i][j][1], sc[j][1], bi[j][1]);
                v1.x = fmaf(acc[i][j][2], sc[j][0], bi[j][0]);
                v1.y = fmaf(acc[i][j][3], sc[j][1], bi[j][1]);
                *(float2*)(C + (size_t)row0 * Nld + col) = v0;
                *(float2*)(C + (size_t)row1 * Nld + col) = v1;
            }
        }
    }
}

// ---------------------------------------------------------------------------
// In-place row-wise log_softmax over OUT_DIM=1944. One block (256 thr) / row.
// ---------------------------------------------------------------------------
__global__ void logsoftmax_kernel(float* __restrict__ out) {
    const int N = OUT_DIM;
    float* row = out + (size_t)blockIdx.x * N;
    const int tid = threadIdx.x;

    float v[8];
    float mx = -1e30f;
    #pragma unroll
    for (int j = 0; j < 8; ++j) {
        int c = tid + j * 256;
        v[j] = (c < N) ? row[c] : -1e30f;
        mx = fmaxf(mx, v[j]);
    }

    __shared__ float red_max[8];
    __shared__ float red_sum[8];
    #pragma unroll
    for (int o = 16; o > 0; o >>= 1)
        mx = fmaxf(mx, __shfl_xor_sync(0xffffffffu, mx, o));
    if ((tid & 31) == 0) red_max[tid >> 5] = mx;
    __syncthreads();
    mx = red_max[0];
    #pragma unroll
    for (int w = 1; w < 8; ++w) mx = fmaxf(mx, red_max[w]);

    float s = 0.f;
    #pragma unroll
    for (int j = 0; j < 8; ++j) s += expf(v[j] - mx);
    #pragma unroll
    for (int o = 16; o > 0; o >>= 1)
        s += __shfl_xor_sync(0xffffffffu, s, o);
    if ((tid & 31) == 0) red_sum[tid >> 5] = s;
    __syncthreads();
    s = 0.f;
    #pragma unroll
    for (int w = 0; w < 8; ++w) s += red_sum[w];

    const float lse = mx + logf(s);
    #pragma unroll
    for (int j = 0; j < 8; ++j) {
        int c = tid + j * 256;
        if (c < N) row[c] = v[j] - lse;
    }
}

// ---------------------------------------------------------------------------
// Launch sequence
// ---------------------------------------------------------------------------
#define GEMM_SMEM 65536

extern "C" void kernel_launch(void* const* d_in, const int* in_sizes, int n_in,
                              void* d_out, int out_size) {
    const float* xs   = (const float*)d_in[0];
    const float* W0   = (const float*)d_in[1];
    const float* Ws   = (const float*)d_in[2];
    const float* taus = (const float*)d_in[3];
    const float* bng  = (const float*)d_in[4];
    const float* bnb  = (const float*)d_in[5];
    const float* Wf   = (const float*)d_in[6];
    const float* fg   = (const float*)d_in[7];
    const float* fb   = (const float*)d_in[8];
    float* out = (float*)d_out;

    __nv_bfloat16 *actIn, *act0, *act1, *w0cat, *wscat, *wf;
    float* wsb;
    cudaGetSymbolAddress((void**)&actIn, g_actIn);
    cudaGetSymbolAddress((void**)&act0,  g_act0);
    cudaGetSymbolAddress((void**)&act1,  g_act1);
    cudaGetSymbolAddress((void**)&wsb,   g_ws);
    cudaGetSymbolAddress((void**)&w0cat, g_w0cat);
    cudaGetSymbolAddress((void**)&wscat, g_wscat);
    cudaGetSymbolAddress((void**)&wf,    g_wf);

    cudaFuncSetAttribute(gemm_hmma_kernel,
                         cudaFuncAttributeMaxDynamicSharedMemorySize, GEMM_SMEM);

    // weight preparation
    split_weights_kernel<<<(HID * IN_PAD + 255) / 256, 256>>>(
        W0, w0cat, HID, IN_DIM, IN_PAD);
    split_weights_kernel<<<(3 * HID * HID + 255) / 256, 256>>>(
        Ws, wscat, 3 * HID, HID, HID);
    convert_weights_kernel<<<(OUT_DIM * HID + 255) / 256, 256>>>(
        Wf, wf, OUT_DIM * HID);

    // input spike quantization scan (scalar lanes, explicit prefetch)
    input_scan_kernel<<<(BATCH * IN_PAD + 255) / 256, 256>>>(xs, actIn);

    const dim3 grid_h(HID / 128, MROWS / 128);   // 8 x 250

    // layer 0 (Kphys = 448 padded, Kv = 896 hi|lo)
    gemm_hmma_kernel<<<grid_h, 256, GEMM_SMEM>>>(
        actIn, w0cat, bng, bnb, wsb, HID, HID, IN_PAD, 2 * IN_PAD, 2 * IN_PAD);
    lif_scan_kernel<<<(BATCH * HID) / 256, 256>>>(wsb, taus, act0);

    // layers 1..3 (ping-pong), Kv = 2048 hi|lo
    __nv_bfloat16* src = act0;
    __nv_bfloat16* dst = act1;
    for (int l = 1; l < 4; ++l) {
        gemm_hmma_kernel<<<grid_h, 256, GEMM_SMEM>>>(
            src, wscat + (size_t)(l - 1) * HID * 2 * HID,
            bng + l * HID, bnb + l * HID, wsb, HID, HID, HID, 2 * HID, 2 * HID);
        lif_scan_kernel<<<(BATCH * HID) / 256, 256>>>(wsb, taus + l * HID, dst);
        __nv_bfloat16* tmp = src; src = dst; dst = tmp;
    }

    // final GEMM (hi-only bf16 weights, Kv = 1024) + BN into d_out
    gemm_hmma_kernel<<<dim3((OUT_DIM + 127) / 128, MROWS / 128), 256, GEMM_SMEM>>>(
        src, wf, fg, fb, out, OUT_DIM, OUT_DIM, HID, HID, HID);
    logsoftmax_kernel<<<MROWS, 256>>>(out);
}

// round 15
// speedup vs baseline: 1.1817x; 1.0055x over previous
#include <cuda_runtime.h>
#include <cuda_bf16.h>
#include <math.h>
#include <stdint.h>

// ---------------------------------------------------------------------------
// TraditionalSpikingModel via HMMA (mma.sync bf16) — tcgen05 unavailable
// (harness emits compute_103 non-'a' PTX).
//
// Hidden layers: weights split w = hi(bf16) + lo(bf16), one GEMM with virtual
// K' = 2K (A pointer wraps at K) -> fp32-grade accuracy. Final layer hi-only.
// GEMM: 128x128x32, 8 warps, 4-stage cp.async pipeline, one barrier/K-step.
// Scans: scalar lane/thread, explicit depth-20 prefetch + __ldcs streaming.
// Final GEMM+softmax chunked in 2 M-halves for L2 locality of logits.
// ---------------------------------------------------------------------------

#define T_STEPS 500
#define BATCH   64
#define IN_DIM  440
#define IN_PAD  448
#define HID     1024
#define OUT_DIM 1944
#define MROWS   (T_STEPS * BATCH)        // 32000
#define QMAXF   7.0f
#define INV_SQRT_BN 0.9999950000374997f  // 1/sqrt(1 + 1e-5)
#define CHUNK   20

// ---------------- device scratch (allocation-free rule) --------------------
__device__ __nv_bfloat16 g_actIn[(size_t)MROWS * IN_PAD];
__device__ __nv_bfloat16 g_act0[(size_t)MROWS * HID];
__device__ __nv_bfloat16 g_act1[(size_t)MROWS * HID];
__device__ float         g_ws[(size_t)MROWS * HID];
__device__ __nv_bfloat16 g_w0cat[(size_t)HID * 2 * IN_PAD];
__device__ __nv_bfloat16 g_wscat[(size_t)3 * HID * 2 * HID];
__device__ __nv_bfloat16 g_wf[(size_t)OUT_DIM * HID];

// ---------------------------- small helpers --------------------------------
__device__ __forceinline__ uint32_t smem_u32(const void* p) {
    uint32_t a;
    asm("{ .reg .u64 t; cvta.to.shared.u64 t, %1; cvt.u32.u64 %0, t; }"
        : "=r"(a) : "l"(p));
    return a;
}

__device__ __forceinline__ void cp_async16(uint32_t dst, const void* src, uint32_t src_bytes) {
    asm volatile("cp.async.cg.shared.global [%0], [%1], 16, %2;"
                 :: "r"(dst), "l"(src), "r"(src_bytes) : "memory");
}
#define CP_COMMIT() asm volatile("cp.async.commit_group;" ::: "memory")
#define CP_WAIT(n)  asm volatile("cp.async.wait_group %0;" :: "n"(n) : "memory")

__device__ __forceinline__ void ldmatrix_x4(uint32_t& r0, uint32_t& r1,
                                            uint32_t& r2, uint32_t& r3,
                                            uint32_t addr) {
    asm volatile("ldmatrix.sync.aligned.m8n8.x4.shared.b16 {%0,%1,%2,%3}, [%4];"
                 : "=r"(r0), "=r"(r1), "=r"(r2), "=r"(r3) : "r"(addr));
}

__device__ __forceinline__ void mma_bf16(float* c, const uint32_t* a, const uint32_t* b) {
    asm volatile(
        "mma.sync.aligned.m16n8k16.row.col.f32.bf16.bf16.f32 "
        "{%0,%1,%2,%3}, {%4,%5,%6,%7}, {%8,%9}, {%0,%1,%2,%3};"
        : "+f"(c[0]), "+f"(c[1]), "+f"(c[2]), "+f"(c[3])
        : "r"(a[0]), "r"(a[1]), "r"(a[2]), "r"(a[3]), "r"(b[0]), "r"(b[1]));
}

// swizzled byte offset inside a 128x32 bf16 tile (row = 64B, 4x16B chunks)
__device__ __forceinline__ uint32_t tile_off(int r, int c4) {
    return (uint32_t)(r * 64 + ((c4 ^ ((r >> 1) & 3)) << 4));
}

// ---------------------------------------------------------------------------
// Weight split: dst[n][k] = bf16_hi(w), dst[n][Kp + k] = bf16(w - hi)
// ---------------------------------------------------------------------------
__global__ void split_weights_kernel(const float* __restrict__ src,
                                     __nv_bfloat16* __restrict__ dst,
                                     int N, int K, int Kp) {
    int idx = blockIdx.x * blockDim.x + threadIdx.x;
    if (idx >= N * Kp) return;
    int n = idx / Kp, k = idx - n * Kp;
    float w = (k < K) ? src[(size_t)n * K + k] : 0.f;
    __nv_bfloat16 hi = __float2bfloat16(w);
    float lo = w - __bfloat162float(hi);
    dst[(size_t)n * (2 * Kp) + k]      = hi;
    dst[(size_t)n * (2 * Kp) + Kp + k] = __float2bfloat16(lo);
}

// plain fp32 -> bf16 convert (final-layer weights, hi only)
__global__ void convert_weights_kernel(const float* __restrict__ src,
                                       __nv_bfloat16* __restrict__ dst, int n) {
    int idx = blockIdx.x * blockDim.x + threadIdx.x;
    if (idx < n) dst[idx] = __float2bfloat16(src[idx]);
}

// ---------------------------------------------------------------------------
// Input scan -> bf16 spikes, padded to IN_PAD cols. Scalar lane/thread,
// explicit depth-20 prefetch (T=500 = 25 x 20), streaming loads.
// ---------------------------------------------------------------------------
__global__ void input_scan_kernel(const float* __restrict__ xs,
                                  __nv_bfloat16* __restrict__ spk) {
    const int L = BATCH * IN_PAD;
    int idx = blockIdx.x * blockDim.x + threadIdx.x;
    if (idx >= L) return;
    int b = idx / IN_PAD, i = idx - b * IN_PAD;
    const bool valid = (i < IN_DIM);
    const float* xp = xs + (size_t)b * IN_DIM + i;
    float vmem = 0.f;
    float x[CHUNK];

    for (int t0 = 0; t0 < T_STEPS; t0 += CHUNK) {
        #pragma unroll
        for (int j = 0; j < CHUNK; ++j)
            x[j] = valid ? __ldcs(xp + (size_t)(t0 + j) * (BATCH * IN_DIM)) : 0.f;
        #pragma unroll
        for (int j = 0; j < CHUNK; ++j) {
            vmem += x[j];
            float o = fminf(fmaxf(rintf(vmem), 0.f), QMAXF);
            spk[(size_t)(t0 + j) * L + idx] = __float2bfloat16(o);
            vmem -= o;
        }
    }
}

// ---------------------------------------------------------------------------
// LIF scan: fp32 ws in (streaming, read-once), bf16 spikes out. Scalar
// lane/thread, explicit depth-20 prefetch. Arithmetic order unchanged.
// ---------------------------------------------------------------------------
__global__ void lif_scan_kernel(const float* __restrict__ ws,
                                const float* __restrict__ taus,
                                __nv_bfloat16* __restrict__ spk) {
    const int L = BATCH * HID;
    int idx = blockIdx.x * blockDim.x + threadIdx.x;
    if (idx >= L) return;
    const float tau = taus[idx & (HID - 1)];
    float syn = 0.f, vmem = 0.f;
    float x[CHUNK];

    for (int t0 = 0; t0 < T_STEPS; t0 += CHUNK) {
        #pragma unroll
        for (int j = 0; j < CHUNK; ++j)
            x[j] = __ldcs(ws + (size_t)(t0 + j) * L + idx);
        #pragma unroll
        for (int j = 0; j < CHUNK; ++j) {
            syn = fmaf(tau, syn, x[j]);
            vmem += syn;
            float o = fminf(fmaxf(rintf(vmem), 0.f), QMAXF);
            spk[(size_t)(t0 + j) * L + idx] = __float2bfloat16(o);
            vmem -= o;
        }
    }
}

// ---------------------------------------------------------------------------
// HMMA GEMM + fused BN over virtual Kv (hi|lo concat or plain):
//   C[m,n] = (sum_k A[m, k % Kphys] * B[n, k]) * gamma[n]*INV + beta[n]
// CTA 128x128, BK=32, 256 thr (8 warps 4x2, warp tile 32x64).
// 4-stage cp.async pipeline, ONE barrier per K-step.
// ---------------------------------------------------------------------------
__global__ void __launch_bounds__(256, 2)
gemm_hmma_kernel(const __nv_bfloat16* __restrict__ A,
                 const __nv_bfloat16* __restrict__ B,
                 const float* __restrict__ gamma,
                 const float* __restrict__ beta,
                 float* __restrict__ C,
                 int N, int Nld, int Kphys, int Kv, int Bstride) {
    extern __shared__ __align__(128) char smem[];
    const uint32_t sm0 = smem_u32(smem);   // A stages at 0..32KB, B at 32..64KB

    const int tid  = threadIdx.x;
    const int wid  = tid >> 5;
    const int lane = tid & 31;
    const int wm   = wid & 3;
    const int wn   = wid >> 2;
    const int m0   = blockIdx.y * 128;
    const int n0   = blockIdx.x * 128;

    const int nsteps = Kv / 32;

    const int r0 = tid >> 2;
    const int c4 = tid & 3;

    const int brow0 = n0 + r0, brow1 = n0 + r0 + 64;
    const uint32_t bsz0 = (brow0 < N) ? 16u : 0u;
    const uint32_t bsz1 = (brow1 < N) ? 16u : 0u;
    const __nv_bfloat16* Bp0 = B + (size_t)min(brow0, N - 1) * Bstride + c4 * 8;
    const __nv_bfloat16* Bp1 = B + (size_t)min(brow1, N - 1) * Bstride + c4 * 8;
    const __nv_bfloat16* Ap0 = A + (size_t)(m0 + r0) * Kphys + c4 * 8;
    const __nv_bfloat16* Ap1 = A + (size_t)(m0 + r0 + 64) * Kphys + c4 * 8;
    const uint32_t dA0 = tile_off(r0, c4), dA1 = tile_off(r0 + 64, c4);

    #define ISSUE_LOAD(s)                                                        \
    do {                                                                         \
        int k0 = (s) * 32;                                                       \
        int kA = (k0 >= Kphys) ? (k0 - Kphys) : k0;                              \
        uint32_t aB = sm0 + (uint32_t)((s) & 3) * 8192u;                         \
        uint32_t bB = aB + 32768u;                                               \
        cp_async16(aB + dA0, Ap0 + kA, 16u);                                     \
        cp_async16(aB + dA1, Ap1 + kA, 16u);                                     \
        cp_async16(bB + dA0, Bp0 + k0, bsz0);                                    \
        cp_async16(bB + dA1, Bp1 + k0, bsz1);                                    \
        CP_COMMIT();                                                             \
    } while (0)

    const int aRow = wm * 32 + (lane & 15);
    const int aKc  = lane >> 4;
    const int bRow = wn * 64 + (lane & 7) + ((lane >> 4) << 3);
    const int bKc  = (lane >> 3) & 1;

    float acc[2][8][4];
    #pragma unroll
    for (int i = 0; i < 2; ++i)
        #pragma unroll
        for (int j = 0; j < 8; ++j)
            #pragma unroll
            for (int q = 0; q < 4; ++q) acc[i][j][q] = 0.f;

    ISSUE_LOAD(0);
    ISSUE_LOAD(1);
    ISSUE_LOAD(2);

    for (int s = 0; s < nsteps; ++s) {
        if (s + 2 < nsteps)      { CP_WAIT(2); }
        else if (s + 1 < nsteps) { CP_WAIT(1); }
        else                     { CP_WAIT(0); }
        __syncthreads();
        if (s + 3 < nsteps) ISSUE_LOAD(s + 3);

        const uint32_t sAb = sm0 + (uint32_t)(s & 3) * 8192u;
        const uint32_t sBb = sAb + 32768u;

        #pragma unroll
        for (int ks = 0; ks < 2; ++ks) {
            uint32_t a[2][4], b[4][4];
            #pragma unroll
            for (int i = 0; i < 2; ++i) {
                int rr = aRow + i * 16;
                uint32_t ad = sAb + tile_off(rr, ks * 2 + aKc);
                ldmatrix_x4(a[i][0], a[i][1], a[i][2], a[i][3], ad);
            }
            #pragma unroll
            for (int p = 0; p < 4; ++p) {
                int rr = bRow + p * 16;
                uint32_t bd = sBb + tile_off(rr, ks * 2 + bKc);
                ldmatrix_x4(b[p][0], b[p][1], b[p][2], b[p][3], bd);
            }
            #pragma unroll
            for (int i = 0; i < 2; ++i)
                #pragma unroll
                for (int p = 0; p < 4; ++p) {
                    mma_bf16(acc[i][2 * p],     a[i], &b[p][0]);
                    mma_bf16(acc[i][2 * p + 1], a[i], &b[p][2]);
                }
        }
    }
    #undef ISSUE_LOAD

    // ---- epilogue: fused BN, float2 stores ----
    const int colBase = n0 + wn * 64 + (lane & 3) * 2;
    float sc[8][2], bi[8][2];
    #pragma unroll
    for (int j = 0; j < 8; ++j) {
        int col = colBase + j * 8;
        bool v = col < N;
        sc[j][0] = v ? gamma[col] * INV_SQRT_BN : 0.f;
        sc[j][1] = v ? gamma[col + 1] * INV_SQRT_BN : 0.f;
        bi[j][0] = v ? beta[col] : 0.f;
        bi[j][1] = v ? beta[col + 1] : 0.f;
    }

    const int rowBase = m0 + wm * 32 + (lane >> 2);
    #pragma unroll
    for (int i = 0; i < 2; ++i) {
        int row0 = rowBase + i * 16;
        int row1 = row0 + 8;
        #pragma unroll
        for (int j = 0; j < 8; ++j) {
            int col = colBase + j * 8;
            if (col < N) {
                float2 v0, v1;
                v0.x = fmaf(acc[i][j][0], sc[j][0], bi[j][0]);
                v0.y = fmaf(acc[i][j][1], sc[j][1], bi[j][1]);
                v1.x = fmaf(acc[i][j][2], sc[j][0], bi[j][0]);
                v1.y = fmaf(acc[i][j][3], sc[j][1], bi[j][1]);
                *(float2*)(C + (size_t)row0 * Nld + col) = v0;
                *(float2*)(C + (size_t)row1 * Nld + col) = v1;
            }
        }
    }
}

// ---------------------------------------------------------------------------
// In-place row-wise log_softmax over OUT_DIM=1944. One block (256 thr) / row.
// ---------------------------------------------------------------------------
__global__ void logsoftmax_kernel(float* __restrict__ out) {
    const int N = OUT_DIM;
    float* row = out + (size_t)blockIdx.x * N;
    const int tid = threadIdx.x;

    float v[8];
    float mx = -1e30f;
    #pragma unroll
    for (int j = 0; j < 8; ++j) {
        int c = tid + j * 256;
        v[j] = (c < N) ? row[c] : -1e30f;
        mx = fmaxf(mx, v[j]);
    }

    __shared__ float red_max[8];
    __shared__ float red_sum[8];
    #pragma unroll
    for (int o = 16; o > 0; o >>= 1)
        mx = fmaxf(mx, __shfl_xor_sync(0xffffffffu, mx, o));
    if ((tid & 31) == 0) red_max[tid >> 5] = mx;
    __syncthreads();
    mx = red_max[0];
    #pragma unroll
    for (int w = 1; w < 8; ++w) mx = fmaxf(mx, red_max[w]);

    float s = 0.f;
    #pragma unroll
    for (int j = 0; j < 8; ++j) s += expf(v[j] - mx);
    #pragma unroll
    for (int o = 16; o > 0; o >>= 1)
        s += __shfl_xor_sync(0xffffffffu, s, o);
    if ((tid & 31) == 0) red_sum[tid >> 5] = s;
    __syncthreads();
    s = 0.f;
    #pragma unroll
    for (int w = 0; w < 8; ++w) s += red_sum[w];

    const float lse = mx + logf(s);
    #pragma unroll
    for (int j = 0; j < 8; ++j) {
        int c = tid + j * 256;
        if (c < N) row[c] = v[j] - lse;
    }
}

// ---------------------------------------------------------------------------
// Launch sequence
// ---------------------------------------------------------------------------
#define GEMM_SMEM 65536

extern "C" void kernel_launch(void* const* d_in, const int* in_sizes, int n_in,
                              void* d_out, int out_size) {
    const float* xs   = (const float*)d_in[0];
    const float* W0   = (const float*)d_in[1];
    const float* Ws   = (const float*)d_in[2];
    const float* taus = (const float*)d_in[3];
    const float* bng  = (const float*)d_in[4];
    const float* bnb  = (const float*)d_in[5];
    const float* Wf   = (const float*)d_in[6];
    const float* fg   = (const float*)d_in[7];
    const float* fb   = (const float*)d_in[8];
    float* out = (float*)d_out;

    __nv_bfloat16 *actIn, *act0, *act1, *w0cat, *wscat, *wf;
    float* wsb;
    cudaGetSymbolAddress((void**)&actIn, g_actIn);
    cudaGetSymbolAddress((void**)&act0,  g_act0);
    cudaGetSymbolAddress((void**)&act1,  g_act1);
    cudaGetSymbolAddress((void**)&wsb,   g_ws);
    cudaGetSymbolAddress((void**)&w0cat, g_w0cat);
    cudaGetSymbolAddress((void**)&wscat, g_wscat);
    cudaGetSymbolAddress((void**)&wf,    g_wf);

    cudaFuncSetAttribute(gemm_hmma_kernel,
                         cudaFuncAttributeMaxDynamicSharedMemorySize, GEMM_SMEM);

    // weight preparation
    split_weights_kernel<<<(HID * IN_PAD + 255) / 256, 256>>>(
        W0, w0cat, HID, IN_DIM, IN_PAD);
    split_weights_kernel<<<(3 * HID * HID + 255) / 256, 256>>>(
        Ws, wscat, 3 * HID, HID, HID);
    convert_weights_kernel<<<(OUT_DIM * HID + 255) / 256, 256>>>(
        Wf, wf, OUT_DIM * HID);

    // input spike quantization scan
    input_scan_kernel<<<(BATCH * IN_PAD + 255) / 256, 256>>>(xs, actIn);

    const dim3 grid_h(HID / 128, MROWS / 128);   // 8 x 250

    // layer 0 (Kphys = 448 padded, Kv = 896 hi|lo)
    gemm_hmma_kernel<<<grid_h, 256, GEMM_SMEM>>>(
        actIn, w0cat, bng, bnb, wsb, HID, HID, IN_PAD, 2 * IN_PAD, 2 * IN_PAD);
    lif_scan_kernel<<<(BATCH * HID) / 256, 256>>>(wsb, taus, act0);

    // layers 1..3 (ping-pong), Kv = 2048 hi|lo
    __nv_bfloat16* src = act0;
    __nv_bfloat16* dst = act1;
    for (int l = 1; l < 4; ++l) {
        gemm_hmma_kernel<<<grid_h, 256, GEMM_SMEM>>>(
            src, wscat + (size_t)(l - 1) * HID * 2 * HID,
            bng + l * HID, bnb + l * HID, wsb, HID, HID, HID, 2 * HID, 2 * HID);
        lif_scan_kernel<<<(BATCH * HID) / 256, 256>>>(wsb, taus + l * HID, dst);
        __nv_bfloat16* tmp = src; src = dst; dst = tmp;
    }

    // final GEMM (hi-only, Kv = 1024) + BN + log_softmax, 2 M-chunks so the
    // softmax reads its logits while they are still L2-resident.
    const int HALF = MROWS / 2;                  // 16000 rows
    for (int c = 0; c < 2; ++c) {
        const __nv_bfloat16* aC = src + (size_t)c * HALF * HID;
        float* oC = out + (size_t)c * HALF * OUT_DIM;
        gemm_hmma_kernel<<<dim3((OUT_DIM + 127) / 128, HALF / 128), 256, GEMM_SMEM>>>(
            aC, wf, fg, fb, oC, OUT_DIM, OUT_DIM, HID, HID, HID);
        logsoftmax_kernel<<<HALF, 256>>>(oC);
    }
}